// round 15
// baseline (speedup 1.0000x reference)
#include <cuda_runtime.h>
#include <cuda_bf16.h>

#define KST   256
#define DIM   256
#define VOC   50000
#define TT    512
#define BBAT  256
#define KP1   257
#define MDIM  512
#define NROWS (KP1*KP1)
#define NTILES 2065          // ceil(NROWS/32)
#define LN_EPS 1e-5f
#define NEGINF (__int_as_float(0xff800000))
#define NCB   391            // ceil(50000/128)

__device__ __nv_bfloat16 g_h_bf[KST*DIM];
__device__ float g_h32[KST*DIM];
__device__ float g_P[KP1*MDIM];
__device__ float g_Q[KP1*MDIM];
__device__ __nv_bfloat16 g_tdw_bf[KST*MDIM];
__device__ __nv_bfloat16 g_th[(size_t)NROWS*MDIM];
__device__ float g_logZ_em[KST];
__device__ float g_em_pmax[KST*NCB];
__device__ float g_em_psum[KST*NCB];
__device__ float g_translp[(size_t)NROWS*KST];
__device__ float2 g_tpart[2*NROWS];
__device__ float g_translse[NROWS];
__device__ float g_epart[BBAT*8];

__device__ __forceinline__ void mma16816(float* c,
    unsigned a0, unsigned a1, unsigned a2, unsigned a3, unsigned b0, unsigned b1)
{
    asm volatile(
        "mma.sync.aligned.m16n8k16.row.col.f32.bf16.bf16.f32 "
        "{%0,%1,%2,%3}, {%4,%5,%6,%7}, {%8,%9}, {%0,%1,%2,%3};\n"
        : "+f"(c[0]), "+f"(c[1]), "+f"(c[2]), "+f"(c[3])
        : "r"(a0), "r"(a1), "r"(a2), "r"(a3), "r"(b0), "r"(b1));
}
__device__ __forceinline__ void ldsm4(unsigned& r0, unsigned& r1, unsigned& r2, unsigned& r3,
                                      unsigned addr)
{
    asm volatile("ldmatrix.sync.aligned.m8n8.x4.shared.b16 {%0,%1,%2,%3}, [%4];"
        : "=r"(r0), "=r"(r1), "=r"(r2), "=r"(r3) : "r"(addr));
}
__device__ __forceinline__ unsigned smem_u32(const void* p)
{
    return (unsigned)__cvta_generic_to_shared(p);
}
__device__ __forceinline__ void cp16(void* dst_smem, const void* src)
{
    unsigned d = smem_u32(dst_smem);
    asm volatile("cp.async.cg.shared.global [%0], [%1], 16;\n" :: "r"(d), "l"(src));
}
__device__ __forceinline__ unsigned bf2u(__nv_bfloat162 v)
{
    return *reinterpret_cast<unsigned*>(&v);
}
__device__ __forceinline__ float2 u2f2(unsigned u)
{
    __nv_bfloat162 b = *reinterpret_cast<__nv_bfloat162*>(&u);
    return __bfloat1622float2(b);
}
__device__ __forceinline__ uint4 f8_to_bf8(float4 a, float4 b)
{
    uint4 v;
    v.x = bf2u(__floats2bfloat162_rn(a.x, a.y));
    v.y = bf2u(__floats2bfloat162_rn(a.z, a.w));
    v.z = bf2u(__floats2bfloat162_rn(b.x, b.y));
    v.w = bf2u(__floats2bfloat162_rn(b.z, b.w));
    return v;
}

// ---- A: emission MLP -> h (fp32 + bf16) ; one block per state k ----
__global__ __launch_bounds__(DIM) void nhmm_kA(
    const float* __restrict__ lembs, const float* __restrict__ emW,
    const float* __restrict__ em_bias, const float* __restrict__ em_g,
    const float* __restrict__ em_beta)
{
    __shared__ float le[DIM];
    __shared__ float ws[8], ws2[8];
    int k = blockIdx.x, c = threadIdx.x;
    le[c] = lembs[k*DIM + c];
    __syncthreads();
    const float4* w4 = reinterpret_cast<const float4*>(emW + (size_t)c*DIM);
    float acc = 0.f;
    #pragma unroll 8
    for (int d4 = 0; d4 < DIM/4; d4++) {
        float4 w = w4[d4];
        acc += le[4*d4]*w.x + le[4*d4+1]*w.y + le[4*d4+2]*w.z + le[4*d4+3]*w.w;
    }
    float p = le[c] + fmaxf(acc + em_bias[c], 0.f);
    float s = p, s2 = p*p;
    #pragma unroll
    for (int o = 16; o; o >>= 1) {
        s  += __shfl_xor_sync(0xffffffffu, s,  o);
        s2 += __shfl_xor_sync(0xffffffffu, s2, o);
    }
    if ((c & 31) == 0) { ws[c>>5] = s; ws2[c>>5] = s2; }
    __syncthreads();
    float S = 0.f, S2 = 0.f;
    #pragma unroll
    for (int w = 0; w < 8; w++) { S += ws[w]; S2 += ws2[w]; }
    float mu = S * (1.f/DIM);
    float rstd = rsqrtf(S2*(1.f/DIM) - mu*mu + LN_EPS);
    float h = (p - mu)*rstd*em_g[c] + em_beta[c];
    g_h32[k*DIM + c] = h;
    g_h_bf[k*DIM + c] = __float2bfloat16(h);
}

// ---- B2: P,Q = tlembs @ tm_W halves ; block = 8 i-rows x 256 out cols ----
__global__ __launch_bounds__(256) void nhmm_kB2(
    const float* __restrict__ tlembs, const float* __restrict__ tmW,
    const float* __restrict__ tm_bias)
{
    __shared__ float tl[8][DIM];
    int ib = blockIdx.x;            // 0..32
    int cgrp = blockIdx.y;          // 0..3
    int t = threadIdx.x;
    int i0 = ib*8;
    {
        int e = t*8;
        int r = e >> 8, c = e & 255;
        const float4* s4 = reinterpret_cast<const float4*>(&tlembs[min(i0+r,KP1-1)*DIM + c]);
        *reinterpret_cast<float4*>(&tl[r][c])   = s4[0];
        *reinterpret_cast<float4*>(&tl[r][c+4]) = s4[1];
    }
    __syncthreads();
    int cg = cgrp*256 + t;
    bool isP = cg < MDIM;
    int c = isP ? cg : cg - MDIM;
    const float4* w4 = reinterpret_cast<const float4*>(
        tmW + (size_t)c*MDIM + (isP ? 0 : DIM));
    float acc[8] = {};
    #pragma unroll 8
    for (int d4 = 0; d4 < DIM/4; d4++) {
        float4 w = w4[d4];
        #pragma unroll
        for (int i = 0; i < 8; i++) {
            acc[i] += tl[i][4*d4]*w.x + tl[i][4*d4+1]*w.y
                    + tl[i][4*d4+2]*w.z + tl[i][4*d4+3]*w.w;
        }
    }
    float bias = isP ? tm_bias[c] : 0.f;
    float* dst = isP ? g_P : g_Q;
    #pragma unroll
    for (int i = 0; i < 8; i++)
        if (i0 + i < KP1) dst[(i0+i)*MDIM + c] = acc[i] + bias;
}

// ---- conv: td_W -> bf16 ----
__global__ void nhmm_kConv(const float* __restrict__ tdW)
{
    int idx = blockIdx.x*blockDim.x + threadIdx.x;
    if (idx < KST*MDIM) g_tdw_bf[idx] = __float2bfloat16(tdW[idx]);
}

// ---- C: emission partial logsumexp over V ----
#define C_WSTR 264
#define C_ASTR 264
#define C_SMEM 102912
__global__ __launch_bounds__(256) void nhmm_kC(
    const float* __restrict__ decW, const float* __restrict__ decb)
{
    extern __shared__ char sm[];
    __nv_bfloat16* W_s = reinterpret_cast<__nv_bfloat16*>(sm);
    __nv_bfloat16* A_s = reinterpret_cast<__nv_bfloat16*>(sm + 67584);
    float* decb_s = reinterpret_cast<float*>(sm + 101376);
    float2* red   = reinterpret_cast<float2*>(sm + 101888);

    int cb = blockIdx.x;
    int n0 = cb * 128;
    int tid = threadIdx.x, warp = tid >> 5, lane = tid & 31;
    int wr = warp >> 1, wc = warp & 1;
    int gid = lane >> 2, tg = lane & 3;

    {
        int n = tid >> 1, k0 = (tid & 1) * 128;
        bool valid = (n0 + n) < VOC;
        const float4* src = reinterpret_cast<const float4*>(decW + (size_t)(n0+n)*DIM + k0);
        uint4* dst = reinterpret_cast<uint4*>(&W_s[n*C_WSTR + k0]);
        #pragma unroll
        for (int u = 0; u < 16; u++) {
            float4 a = valid ? src[2*u]   : make_float4(0.f,0.f,0.f,0.f);
            float4 b = valid ? src[2*u+1] : make_float4(0.f,0.f,0.f,0.f);
            dst[u] = f8_to_bf8(a, b);
        }
    }
    if (tid < 128) decb_s[tid] = (n0 + tid < VOC) ? decb[n0 + tid] : 0.f;

    unsigned A_u = smem_u32(A_s), W_u = smem_u32(W_s);
    int a_row = wr*16 + (lane & 15);
    int a_k8  = (lane >> 4) * 8;
    unsigned a_base = A_u + (unsigned)(a_row*C_ASTR + a_k8)*2u;
    int b_r = lane & 7, b_seg = lane >> 3;
    int b_row0 = ((b_seg >> 1) & 1)*8 + b_r;
    int b_k8 = (b_seg & 1)*8;
    unsigned b_base = W_u + (unsigned)(b_row0*C_WSTR + b_k8)*2u;

    for (int rb = 0; rb < 4; rb++) {
        int r0 = rb * 64;
        __syncthreads();
        {
            int row = tid >> 2, kb = (tid & 3) * 64;
            const uint4* src = reinterpret_cast<const uint4*>(&g_h_bf[(r0+row)*DIM + kb]);
            uint4* dst = reinterpret_cast<uint4*>(&A_s[row*C_ASTR + kb]);
            #pragma unroll
            for (int u = 0; u < 8; u++) dst[u] = src[u];
        }
        __syncthreads();

        float acc[8][4] = {};
        #pragma unroll
        for (int k = 0; k < DIM; k += 16) {
            unsigned a0, a1, a2, a3;
            ldsm4(a0, a1, a2, a3, a_base + (unsigned)k*2u);
            #pragma unroll
            for (int e = 0; e < 4; e++) {
                unsigned b0, b1, b2, b3;
                ldsm4(b0, b1, b2, b3,
                      b_base + (unsigned)((wc*64 + e*16)*C_WSTR + k)*2u);
                mma16816(acc[2*e],   a0, a1, a2, a3, b0, b1);
                mma16816(acc[2*e+1], a0, a1, a2, a3, b2, b3);
            }
        }

        int rA = wr*16 + gid, rB = rA + 8;
        float m0 = NEGINF, m1 = NEGINF;
        float v[8][4];
        #pragma unroll
        for (int f = 0; f < 8; f++) {
            int n = wc*64 + f*8 + 2*tg;
            bool ok0 = (n0 + n) < VOC, ok1 = (n0 + n + 1) < VOC;
            v[f][0] = ok0 ? acc[f][0] + decb_s[n]   : NEGINF;
            v[f][1] = ok1 ? acc[f][1] + decb_s[n+1] : NEGINF;
            v[f][2] = ok0 ? acc[f][2] + decb_s[n]   : NEGINF;
            v[f][3] = ok1 ? acc[f][3] + decb_s[n+1] : NEGINF;
            m0 = fmaxf(m0, fmaxf(v[f][0], v[f][1]));
            m1 = fmaxf(m1, fmaxf(v[f][2], v[f][3]));
        }
        m0 = fmaxf(m0, __shfl_xor_sync(0xffffffffu, m0, 1));
        m0 = fmaxf(m0, __shfl_xor_sync(0xffffffffu, m0, 2));
        m1 = fmaxf(m1, __shfl_xor_sync(0xffffffffu, m1, 1));
        m1 = fmaxf(m1, __shfl_xor_sync(0xffffffffu, m1, 2));
        float s0 = 0.f, s1 = 0.f;
        #pragma unroll
        for (int f = 0; f < 8; f++) {
            s0 += __expf(v[f][0]-m0) + __expf(v[f][1]-m0);
            s1 += __expf(v[f][2]-m1) + __expf(v[f][3]-m1);
        }
        s0 += __shfl_xor_sync(0xffffffffu, s0, 1);
        s0 += __shfl_xor_sync(0xffffffffu, s0, 2);
        s1 += __shfl_xor_sync(0xffffffffu, s1, 1);
        s1 += __shfl_xor_sync(0xffffffffu, s1, 2);
        if (tg == 0) {
            red[rA*2 + wc] = make_float2(m0, s0);
            red[rB*2 + wc] = make_float2(m1, s1);
        }
        __syncthreads();
        if (tid < 64) {
            float2 a = red[tid*2], b = red[tid*2+1];
            float M = fmaxf(a.x, b.x);
            g_em_pmax[(r0+tid)*NCB + cb] = M;
            g_em_psum[(r0+tid)*NCB + cb] = __expf(a.x-M)*a.y + __expf(b.x-M)*b.y;
        }
    }
}

// ---- Cred: combine partial lse -> logZ_em ; one warp per state ----
__global__ __launch_bounds__(32) void nhmm_kCred()
{
    int k = blockIdx.x, lane = threadIdx.x;
    float m = NEGINF;
    for (int cb = lane; cb < NCB; cb += 32) m = fmaxf(m, g_em_pmax[k*NCB + cb]);
    #pragma unroll
    for (int o = 16; o; o >>= 1) m = fmaxf(m, __shfl_xor_sync(0xffffffffu, m, o));
    float s = 0.f;
    for (int cb = lane; cb < NCB; cb += 32)
        s += __expf(g_em_pmax[k*NCB + cb] - m) * g_em_psum[k*NCB + cb];
    #pragma unroll
    for (int o = 16; o; o >>= 1) s += __shfl_xor_sync(0xffffffffu, s, o);
    if (lane == 0) g_logZ_em[k] = m + logf(s);
}

// ---- TH: th = LN(cat + relu(P[i]+Q[j])) -> g_th (bf16) ; 8x8 tile / block ----
__global__ __launch_bounds__(256) void nhmm_kTH(
    const float* __restrict__ tlembs, const float* __restrict__ tn_g,
    const float* __restrict__ tn_beta)
{
    __shared__ __nv_bfloat16 PtB[8*512], QtB[8*512];
    __shared__ __nv_bfloat16 TLiB[8*256], TLjB[8*256];
    __shared__ __nv_bfloat16 g_sb[512], be_sb[512];

    int ib = blockIdx.x, jb = blockIdx.y;
    int tid = threadIdx.x, warp = tid >> 5, lane = tid & 31;

    #pragma unroll
    for (int it = 0; it < 2; it++) {
        int e = (tid + it*256) * 8;
        int r = e >> 9, c = e & 511;
        const float4* s4 = reinterpret_cast<const float4*>(&g_P[min(ib*8+r,256)*MDIM + c]);
        *reinterpret_cast<uint4*>(&PtB[r*512 + c]) = f8_to_bf8(s4[0], s4[1]);
        const float4* q4 = reinterpret_cast<const float4*>(&g_Q[min(jb*8+r,256)*MDIM + c]);
        *reinterpret_cast<uint4*>(&QtB[r*512 + c]) = f8_to_bf8(q4[0], q4[1]);
    }
    {
        int e = tid * 8;
        int r = e >> 8, c = e & 255;
        const float4* s4 = reinterpret_cast<const float4*>(&tlembs[min(ib*8+r,256)*DIM + c]);
        *reinterpret_cast<uint4*>(&TLiB[r*256 + c]) = f8_to_bf8(s4[0], s4[1]);
        const float4* t4 = reinterpret_cast<const float4*>(&tlembs[min(jb*8+r,256)*DIM + c]);
        *reinterpret_cast<uint4*>(&TLjB[r*256 + c]) = f8_to_bf8(t4[0], t4[1]);
    }
    {
        float2 gv = *reinterpret_cast<const float2*>(&tn_g[2*tid]);
        reinterpret_cast<__nv_bfloat162*>(g_sb)[tid] = __floats2bfloat162_rn(gv.x, gv.y);
        float2 bv = *reinterpret_cast<const float2*>(&tn_beta[2*tid]);
        reinterpret_cast<__nv_bfloat162*>(be_sb)[tid] = __floats2bfloat162_rn(bv.x, bv.y);
    }
    __syncthreads();

    for (int q = 0; q < 8; q++) {
        int r = warp*8 + q, ir = r >> 3, jr = r & 7;
        int c0 = lane * 16;
        const uint4* pp = reinterpret_cast<const uint4*>(&PtB[ir*512 + c0]);
        const uint4* qq = reinterpret_cast<const uint4*>(&QtB[jr*512 + c0]);
        const uint4* cc = (c0 < DIM)
            ? reinterpret_cast<const uint4*>(&TLiB[ir*DIM + c0])
            : reinterpret_cast<const uint4*>(&TLjB[jr*DIM + (c0 - DIM)]);
        uint4 pv[2] = {pp[0], pp[1]};
        uint4 qv[2] = {qq[0], qq[1]};
        uint4 cv[2] = {cc[0], cc[1]};
        const unsigned* pw = reinterpret_cast<const unsigned*>(pv);
        const unsigned* qw = reinterpret_cast<const unsigned*>(qv);
        const unsigned* cw = reinterpret_cast<const unsigned*>(cv);
        float vv[16]; float s = 0.f, s2 = 0.f;
        #pragma unroll
        for (int u = 0; u < 8; u++) {
            float2 pf = u2f2(pw[u]), qf = u2f2(qw[u]), cf = u2f2(cw[u]);
            float w0 = cf.x + fmaxf(pf.x + qf.x, 0.f);
            float w1 = cf.y + fmaxf(pf.y + qf.y, 0.f);
            vv[2*u] = w0; vv[2*u+1] = w1;
            s += w0 + w1; s2 += w0*w0 + w1*w1;
        }
        #pragma unroll
        for (int o = 16; o; o >>= 1) {
            s  += __shfl_xor_sync(0xffffffffu, s,  o);
            s2 += __shfl_xor_sync(0xffffffffu, s2, o);
        }
        float mu = s * (1.f/MDIM);
        float rstd = rsqrtf(s2*(1.f/MDIM) - mu*mu + LN_EPS);
        int i = ib*8 + ir, j = jb*8 + jr;
        bool ok = (i < KP1) && (j < KP1);
        size_t rowbase = (size_t)(i*KP1 + j)*MDIM;
        #pragma unroll
        for (int u = 0; u < 2; u++) {
            int cbx = c0 + 8*u;
            uint4 gg = *reinterpret_cast<const uint4*>(&g_sb[cbx]);
            uint4 bb = *reinterpret_cast<const uint4*>(&be_sb[cbx]);
            const unsigned* gw = reinterpret_cast<const unsigned*>(&gg);
            const unsigned* bw = reinterpret_cast<const unsigned*>(&bb);
            float2 g0 = u2f2(gw[0]), g1 = u2f2(gw[1]), g2 = u2f2(gw[2]), g3 = u2f2(gw[3]);
            float2 b0 = u2f2(bw[0]), b1 = u2f2(bw[1]), b2 = u2f2(bw[2]), b3 = u2f2(bw[3]);
            float4 ha, hb;
            ha.x = (vv[8*u  ]-mu)*rstd*g0.x + b0.x;
            ha.y = (vv[8*u+1]-mu)*rstd*g0.y + b0.y;
            ha.z = (vv[8*u+2]-mu)*rstd*g1.x + b1.x;
            ha.w = (vv[8*u+3]-mu)*rstd*g1.y + b1.y;
            hb.x = (vv[8*u+4]-mu)*rstd*g2.x + b2.x;
            hb.y = (vv[8*u+5]-mu)*rstd*g2.y + b2.y;
            hb.z = (vv[8*u+6]-mu)*rstd*g3.x + b3.x;
            hb.w = (vv[8*u+7]-mu)*rstd*g3.y + b3.y;
            if (ok)
                *reinterpret_cast<uint4*>(&g_th[rowbase + cbx]) = f8_to_bf8(ha, hb);
        }
    }
}

// ---- D2: streaming GEMM translp_raw = th @ td_W^T (N-half resident B) ----
// smem: Bt 128x520 bf16 @0 (133120) | A0 @133120 (33280) | A1 @166400 (33280)
//       Ot 32x132 f32 @199680 (16896) | tdb 128 f32 @216576 (512)
//       redq 32x4 float2 @217088 (1024) -> 218112
#define D2_BSTR 520
#define D2_ASTR 520
#define D2_OSTR 132
#define D2_SMEM 218112
__global__ __launch_bounds__(256) void nhmm_kD2(const float* __restrict__ tdb)
{
    extern __shared__ char sm[];
    __nv_bfloat16* Bt = reinterpret_cast<__nv_bfloat16*>(sm);
    __nv_bfloat16* A0 = reinterpret_cast<__nv_bfloat16*>(sm + 133120);
    __nv_bfloat16* A1 = reinterpret_cast<__nv_bfloat16*>(sm + 166400);
    float* Ot    = reinterpret_cast<float*>(sm + 199680);
    float* tdb_s = reinterpret_cast<float*>(sm + 216576);
    float2* redq = reinterpret_cast<float2*>(sm + 217088);

    int sid = blockIdx.x, z = blockIdx.y;
    int tid = threadIdx.x, warp = tid >> 5, lane = tid & 31;
    int wr = warp >> 2, wc = warp & 3;
    int gid = lane >> 2, tg = lane & 3;

    // stage resident B half: rows z*128..z*128+127, k 0..511
    #pragma unroll
    for (int u = 0; u < 32; u++) {
        int op = u*256 + tid;                  // 0..8191
        int n = op >> 6, seg = (op & 63) * 8;
        cp16(&Bt[n*D2_BSTR + seg], &g_tdw_bf[(z*128+n)*MDIM + seg]);
    }
    asm volatile("cp.async.commit_group;\n" ::: "memory");
    if (tid < 128) tdb_s[tid] = tdb[z*128 + tid];

    // prefetch first A tile
    int job = sid;
    #pragma unroll
    for (int u = 0; u < 8; u++) {
        int op = u*256 + tid;                  // 0..2047
        int r = op >> 6, seg = (op & 63) * 8;
        int src = min(job*32 + r, NROWS-1);
        cp16(&A0[r*D2_ASTR + seg], &g_th[(size_t)src*MDIM + seg]);
    }
    asm volatile("cp.async.commit_group;\n" ::: "memory");

    unsigned B_u = smem_u32(Bt);
    unsigned A_us[2] = { smem_u32(A0), smem_u32(A1) };
    int b_r = lane & 7, b_seg = lane >> 3;
    int b_row0 = ((b_seg >> 1) & 1)*8 + b_r;
    int b_k8 = (b_seg & 1)*8;
    unsigned b_base = B_u + (unsigned)(b_row0*D2_BSTR + b_k8)*2u;
    unsigned a_off = (unsigned)((wr*16 + (lane & 15))*D2_ASTR + (lane >> 4)*8)*2u;

    int nb = 0;
    for (; job < NTILES; job += 148) {
        int nxt = job + 148;
        if (nxt < NTILES) {
            __nv_bfloat16* Anext = (nb ? A0 : A1);
            #pragma unroll
            for (int u = 0; u < 8; u++) {
                int op = u*256 + tid;
                int r = op >> 6, seg = (op & 63) * 8;
                int src = min(nxt*32 + r, NROWS-1);
                cp16(&Anext[r*D2_ASTR + seg], &g_th[(size_t)src*MDIM + seg]);
            }
            asm volatile("cp.async.commit_group;\n" ::: "memory");
            asm volatile("cp.async.wait_group 1;\n" ::: "memory");
        } else {
            asm volatile("cp.async.wait_group 0;\n" ::: "memory");
        }
        __syncthreads();

        unsigned a_base = A_us[nb] + a_off;
        float acc[4][4] = {};
        #pragma unroll 8
        for (int k = 0; k < MDIM; k += 16) {
            unsigned a0, a1, a2, a3;
            ldsm4(a0, a1, a2, a3, a_base + (unsigned)k*2u);
            #pragma unroll
            for (int e = 0; e < 2; e++) {
                unsigned b0, b1, b2, b3;
                ldsm4(b0, b1, b2, b3,
                      b_base + (unsigned)((wc*32 + e*16)*D2_BSTR + k)*2u);
                mma16816(acc[2*e],   a0, a1, a2, a3, b0, b1);
                mma16816(acc[2*e+1], a0, a1, a2, a3, b2, b3);
            }
        }

        // epilogue: bias fold + partial lse over this warp's N=32
        int rA = wr*16 + gid, rB = rA + 8;
        float m0 = NEGINF, m1 = NEGINF;
        #pragma unroll
        for (int f = 0; f < 4; f++) {
            int n = wc*32 + f*8 + 2*tg;
            acc[f][0] += tdb_s[n]; acc[f][1] += tdb_s[n+1];
            acc[f][2] += tdb_s[n]; acc[f][3] += tdb_s[n+1];
            m0 = fmaxf(m0, fmaxf(acc[f][0], acc[f][1]));
            m1 = fmaxf(m1, fmaxf(acc[f][2], acc[f][3]));
        }
        m0 = fmaxf(m0, __shfl_xor_sync(0xffffffffu, m0, 1));
        m0 = fmaxf(m0, __shfl_xor_sync(0xffffffffu, m0, 2));
        m1 = fmaxf(m1, __shfl_xor_sync(0xffffffffu, m1, 1));
        m1 = fmaxf(m1, __shfl_xor_sync(0xffffffffu, m1, 2));
        float s0 = 0.f, s1 = 0.f;
        #pragma unroll
        for (int f = 0; f < 4; f++) {
            s0 += __expf(acc[f][0]-m0) + __expf(acc[f][1]-m0);
            s1 += __expf(acc[f][2]-m1) + __expf(acc[f][3]-m1);
        }
        s0 += __shfl_xor_sync(0xffffffffu, s0, 1);
        s0 += __shfl_xor_sync(0xffffffffu, s0, 2);
        s1 += __shfl_xor_sync(0xffffffffu, s1, 1);
        s1 += __shfl_xor_sync(0xffffffffu, s1, 2);
        #pragma unroll
        for (int f = 0; f < 4; f++) {
            int n = wc*32 + f*8 + 2*tg;
            *reinterpret_cast<float2*>(&Ot[rA*D2_OSTR + n]) = make_float2(acc[f][0], acc[f][1]);
            *reinterpret_cast<float2*>(&Ot[rB*D2_OSTR + n]) = make_float2(acc[f][2], acc[f][3]);
        }
        if (tg == 0) {
            redq[rA*4 + wc] = make_float2(m0, s0);
            redq[rB*4 + wc] = make_float2(m1, s1);
        }
        __syncthreads();
        if (tid < 32) {
            int grow = job*32 + tid;
            if (grow < NROWS) {
                float2 p0 = redq[tid*4], p1 = redq[tid*4+1];
                float2 p2 = redq[tid*4+2], p3 = redq[tid*4+3];
                float M = fmaxf(fmaxf(p0.x, p1.x), fmaxf(p2.x, p3.x));
                float S = __expf(p0.x-M)*p0.y + __expf(p1.x-M)*p1.y
                        + __expf(p2.x-M)*p2.y + __expf(p3.x-M)*p3.y;
                g_tpart[(size_t)z*NROWS + grow] = make_float2(M, S);
            }
        }
        {
            int row = tid >> 3, sg = (tid & 7) * 16;
            int grow = job*32 + row;
            if (grow < NROWS) {
                float4* dst = reinterpret_cast<float4*>(&g_translp[(size_t)grow*KST + z*128 + sg]);
                const float4* src = reinterpret_cast<const float4*>(&Ot[row*D2_OSTR + sg]);
                dst[0] = src[0]; dst[1] = src[1]; dst[2] = src[2]; dst[3] = src[3];
            }
        }
        __syncthreads();
        nb ^= 1;
    }
}

// ---- Dred: combine two N-half partials -> g_translse ----
__global__ __launch_bounds__(256) void nhmm_kDred()
{
    int r = blockIdx.x*256 + threadIdx.x;
    if (r < NROWS) {
        float2 a = g_tpart[r], b = g_tpart[NROWS + r];
        float M = fmaxf(a.x, b.x);
        g_translse[r] = M + logf(__expf(a.x-M)*a.y + __expf(b.x-M)*b.y);
    }
}

// ---- E: gather + partial reduction ----
__global__ __launch_bounds__(256) void nhmm_kE(
    const int* __restrict__ x, const int* __restrict__ z,
    const float* __restrict__ decW, const float* __restrict__ decb)
{
    __shared__ float part[8];
    int b = blockIdx.x, ty = blockIdx.y;
    int t0 = ty * 64;
    int tid = threadIdx.x, warp = tid >> 5, lane = tid & 31;
    float accw = 0.f;
    for (int q = 0; q < 8; q++) {
        int t = t0 + warp + 8*q;
        int xv = x[t*BBAT + b], zv = z[t*BBAT + b];
        int w0 = (t >= 2) ? z[(t-2)*BBAT + b] : KST;
        int w1 = (t >= 1) ? z[(t-1)*BBAT + b] : KST;
        const float4* ha = reinterpret_cast<const float4*>(&g_h32[zv*DIM]);
        const float4* wa = reinterpret_cast<const float4*>(&decW[(size_t)xv*DIM]);
        float d = 0.f;
        #pragma unroll
        for (int u = 0; u < 2; u++) {
            float4 hv = ha[lane*2+u], wv = wa[lane*2+u];
            d += hv.x*wv.x + hv.y*wv.y + hv.z*wv.z + hv.w*wv.w;
        }
        #pragma unroll
        for (int o = 16; o; o >>= 1) d += __shfl_xor_sync(0xffffffffu, d, o);
        if (lane == 0) {
            int lin = w0*KP1 + w1;
            accw += d + decb[xv] - g_logZ_em[zv]
                  + g_translp[(size_t)lin*KST + zv] - g_translse[lin];
        }
    }
    if (lane == 0) part[warp] = accw;
    __syncthreads();
    if (tid == 0) {
        float s = 0.f;
        for (int w = 0; w < 8; w++) s += part[w];
        g_epart[b*8 + ty] = s;
    }
}

__global__ __launch_bounds__(BBAT) void nhmm_kEred(float* __restrict__ out)
{
    int b = threadIdx.x;
    float s = 0.f;
    #pragma unroll
    for (int q = 0; q < 8; q++) s += g_epart[b*8 + q];
    out[b] = s;
}

extern "C" void kernel_launch(void* const* d_in, const int* in_sizes, int n_in,
                              void* d_out, int out_size)
{
    const int*   x       = (const int*)d_in[0];
    const int*   z       = (const int*)d_in[1];
    const float* lembs   = (const float*)d_in[2];
    const float* tlembs  = (const float*)d_in[3];
    const float* decW    = (const float*)d_in[4];
    const float* decb    = (const float*)d_in[5];
    const float* emW     = (const float*)d_in[6];
    const float* em_bias = (const float*)d_in[7];
    const float* em_g    = (const float*)d_in[8];
    const float* em_beta = (const float*)d_in[9];
    const float* tdW     = (const float*)d_in[10];
    const float* tdb     = (const float*)d_in[11];
    const float* tmW     = (const float*)d_in[12];
    const float* tm_bias = (const float*)d_in[13];
    const float* tn_g    = (const float*)d_in[14];
    const float* tn_beta = (const float*)d_in[15];
    float* out = (float*)d_out;

    static cudaStream_t s2 = nullptr;
    static cudaEvent_t eFork = nullptr, eJoin = nullptr;
    if (s2 == nullptr) {
        cudaStreamCreateWithFlags(&s2, cudaStreamNonBlocking);
        cudaEventCreateWithFlags(&eFork, cudaEventDisableTiming);
        cudaEventCreateWithFlags(&eJoin, cudaEventDisableTiming);
        cudaFuncSetAttribute(nhmm_kC, cudaFuncAttributeMaxDynamicSharedMemorySize, C_SMEM);
        cudaFuncSetAttribute(nhmm_kD2, cudaFuncAttributeMaxDynamicSharedMemorySize, D2_SMEM);
    }

    // fork: side chain kA -> kC -> kCred on s2
    cudaEventRecord(eFork, 0);
    cudaStreamWaitEvent(s2, eFork, 0);
    nhmm_kA<<<KST, DIM, 0, s2>>>(lembs, emW, em_bias, em_g, em_beta);
    nhmm_kC<<<NCB, 256, C_SMEM, s2>>>(decW, decb);
    nhmm_kCred<<<KST, 32, 0, s2>>>();

    // main chain: kConv -> kB2 -> kTH -> kD2 -> kDred
    nhmm_kConv<<<(KST*MDIM + 255)/256, 256>>>(tdW);
    nhmm_kB2<<<dim3(33, 4), 256>>>(tlembs, tmW, tm_bias);
    nhmm_kTH<<<dim3(33, 33), 256>>>(tlembs, tn_g, tn_beta);
    nhmm_kD2<<<dim3(148, 2), 256, D2_SMEM>>>(tdb);
    nhmm_kDred<<<(NROWS + 255)/256, 256>>>();

    // join, then gather
    cudaEventRecord(eJoin, s2);
    cudaStreamWaitEvent(0, eJoin, 0);
    nhmm_kE<<<dim3(BBAT, 8), 256>>>(x, z, decW, decb);
    nhmm_kEred<<<1, BBAT>>>(out);
}